// round 3
// baseline (speedup 1.0000x reference)
#include <cuda_runtime.h>
#include <cstdint>

#define Bz   32
#define Hd   512
#define Tt   1000
#define G4   2048
#define NBLK 128
#define JPB  4          // hidden units per block
#define NTHR 256
#define KCH  64         // K per k-slice (512 / 8)

// h broadcast buffer, transposed [k][b], double buffered by step parity.
__device__ float    g_hbuf[2][Hd][Bz];
__device__ unsigned g_bar_count = 0;
__device__ unsigned g_bar_gen   = 0;

__device__ __forceinline__ void grid_barrier() {
    __syncthreads();
    if (threadIdx.x == 0) {
        __threadfence();
        unsigned gen = *((volatile unsigned*)&g_bar_gen);
        if (atomicAdd(&g_bar_count, 1u) == NBLK - 1u) {
            atomicExch(&g_bar_count, 0u);
            __threadfence();
            atomicAdd(&g_bar_gen, 1u);
        } else {
            while (*((volatile unsigned*)&g_bar_gen) == gen) { }
        }
        __threadfence();
    }
    __syncthreads();
}

__device__ __forceinline__ float sigf(float x) {
    return 1.0f / (1.0f + __expf(-x));
}

__global__ void __launch_bounds__(NTHR, 1)
lstm_persistent(const float* __restrict__ wx, const float* __restrict__ u,
                const float* __restrict__ ub, const float* __restrict__ h0,
                const float* __restrict__ c0, float* __restrict__ out)
{
    extern __shared__ float sm[];
    float* u_shT = sm;                    // [512][16]  weights, transposed, persistent
    float* h_shT = u_shT + Hd * 16;       // [512][32]  current h, transposed
    float* wx_sh = h_shT + Hd * Bz;       // [16][32]   wx slice for this step
    float* g_sh  = wx_sh + 16 * Bz;       // [16][32]   reduced gate pre-activations
    float* part  = g_sh  + 16 * Bz;       // [8][512]   k-slice partial sums
    float* c_sh  = part  + 8 * 512;       // [4][32]    persistent c state
    float* b_sh  = c_sh  + JPB * Bz;      // [16]       bias slice

    const int tid = threadIdx.x;
    const int blk = blockIdx.x;
    const int j0  = blk * JPB;            // hidden-unit slice [j0, j0+4)

    // ---------------- prologue: load persistent weights / bias / state ----------
    // 16 gate rows of this block: group g (i,f,g,o) row = g*512 + j0 + q
    for (int idx = tid; idx < 16 * Hd; idx += NTHR) {
        int r = idx >> 9;                 // 0..15 local row
        int k = idx & (Hd - 1);
        int R = ((r >> 2) << 9) + j0 + (r & 3);
        u_shT[k * 16 + r] = u[(size_t)R * Hd + k];
    }
    if (tid < 16) {
        int R = ((tid >> 2) << 9) + j0 + (tid & 3);
        b_sh[tid] = ub[R];
    }
    if (tid < JPB * Bz) {
        int jj = tid & 3, b = tid >> 2;
        c_sh[jj * Bz + b] = c0[b * Hd + j0 + jj];
        g_hbuf[0][j0 + jj][b] = h0[b * Hd + j0 + jj];
        __threadfence();
    }
    grid_barrier();

    const int tile = tid & 31;            // 32 tiles of 4b x 4r
    const int ks   = tid >> 5;            // 8 k-slices
    const int bt   = tile & 7;            // b-tile: batches 4*bt..4*bt+3
    const int rt   = tile >> 3;           // r-tile: rows    4*rt..4*rt+3
    const float4* hp4 = reinterpret_cast<const float4*>(h_shT) + bt;
    const float4* up4 = reinterpret_cast<const float4*>(u_shT) + rt;

    const size_t S = (size_t)Bz * Tt * Hd;

    for (int t = 0; t < Tt; t++) {
        const int p = t & 1;

        // ---- broadcast-in: copy hbuf[p] (written last step, L2) into smem ----
        {
            const float4* src = reinterpret_cast<const float4*>(&g_hbuf[p][0][0]);
            float4*       dst = reinterpret_cast<float4*>(h_shT);
            #pragma unroll
            for (int i = 0; i < (Hd * Bz / 4) / NTHR; i++)   // 16 iters
                dst[tid + i * NTHR] = __ldcg(src + tid + i * NTHR);
        }
        // ---- stage wx[:, t, rows] -> wx_sh[r][b] ----
        if (tid < 128) {
            int seg = tid >> 5, b = tid & 31;     // seg = gate group 0..3
            float4 v = __ldg(reinterpret_cast<const float4*>(
                wx + ((size_t)b * Tt + t) * G4 + (seg << 9) + j0));
            wx_sh[(seg * 4 + 0) * Bz + b] = v.x;
            wx_sh[(seg * 4 + 1) * Bz + b] = v.y;
            wx_sh[(seg * 4 + 2) * Bz + b] = v.z;
            wx_sh[(seg * 4 + 3) * Bz + b] = v.w;
        }
        __syncthreads();

        // ---- GEMM: gates_partial[b, r] = sum_k h[b,k] * u[r,k] over this k-slice
        float acc[4][4];
        #pragma unroll
        for (int i = 0; i < 4; i++)
            #pragma unroll
            for (int j = 0; j < 4; j++) acc[i][j] = 0.0f;

        const int k0 = ks * KCH;
        #pragma unroll 8
        for (int k = k0; k < k0 + KCH; k++) {
            float4 hv = hp4[k * 8];      // h for 4 batches at this k
            float4 uv = up4[k * 4];      // u for 4 rows at this k
            acc[0][0] += hv.x * uv.x; acc[0][1] += hv.x * uv.y;
            acc[0][2] += hv.x * uv.z; acc[0][3] += hv.x * uv.w;
            acc[1][0] += hv.y * uv.x; acc[1][1] += hv.y * uv.y;
            acc[1][2] += hv.y * uv.z; acc[1][3] += hv.y * uv.w;
            acc[2][0] += hv.z * uv.x; acc[2][1] += hv.z * uv.y;
            acc[2][2] += hv.z * uv.z; acc[2][3] += hv.z * uv.w;
            acc[3][0] += hv.w * uv.x; acc[3][1] += hv.w * uv.y;
            acc[3][2] += hv.w * uv.z; acc[3][3] += hv.w * uv.w;
        }
        // partials laid out [r][b] so the reduction is fully coalesced in smem
        #pragma unroll
        for (int i = 0; i < 4; i++)
            #pragma unroll
            for (int j = 0; j < 4; j++)
                part[ks * 512 + (rt * 4 + j) * Bz + (bt * 4 + i)] = acc[i][j];
        __syncthreads();

        // ---- reduce 8 k-slices + wx + bias -> g_sh[r][b] ----
        #pragma unroll
        for (int o = tid; o < 512; o += NTHR) {
            float s = wx_sh[o] + b_sh[o >> 5];
            #pragma unroll
            for (int q = 0; q < 8; q++) s += part[q * 512 + o];
            g_sh[o] = s;
        }
        __syncthreads();

        // ---- elementwise LSTM cell + output writes + h broadcast-out ----
        if (tid < JPB * Bz) {
            int jj = tid & 3, b = tid >> 2;
            float xi = g_sh[(0 * 4 + jj) * Bz + b];
            float xf = g_sh[(1 * 4 + jj) * Bz + b];
            float xg = g_sh[(2 * 4 + jj) * Bz + b];
            float xo = g_sh[(3 * 4 + jj) * Bz + b];
            float it = sigf(xi);
            float ft = sigf(xf);
            float gt = tanhf(xg);
            float ot = sigf(xo);
            float c  = ft * c_sh[jj * Bz + b] + it * gt;
            float h  = ot * tanhf(c);
            c_sh[jj * Bz + b] = c;
            g_hbuf[p ^ 1][j0 + jj][b] = h;

            size_t base = ((size_t)b * Tt + t) * Hd + j0 + jj;
            out[base]         = h;
            out[S + base]     = c;
            out[2 * S + base] = it;
            out[3 * S + base] = ft;
            out[4 * S + base] = gt;
            out[5 * S + base] = ot;
            __threadfence();
        }
        grid_barrier();
    }
}

extern "C" void kernel_launch(void* const* d_in, const int* in_sizes, int n_in,
                              void* d_out, int out_size) {
    const float* wx = (const float*)d_in[0];
    const float* u  = (const float*)d_in[1];
    const float* ub = (const float*)d_in[2];
    const float* h0 = (const float*)d_in[3];
    const float* c0 = (const float*)d_in[4];
    float* out = (float*)d_out;

    size_t smem = (size_t)(16 * Hd + Hd * Bz + 16 * Bz + 16 * Bz +
                           8 * 512 + JPB * Bz + 16) * sizeof(float);  // 119360 B
    cudaFuncSetAttribute(lstm_persistent,
                         cudaFuncAttributeMaxDynamicSharedMemorySize, (int)smem);
    lstm_persistent<<<NBLK, NTHR, smem>>>(wx, u, ub, h0, c0, out);
}

// round 4
// speedup vs baseline: 1.0094x; 1.0094x over previous
#include <cuda_runtime.h>
#include <cstdint>

#define Bz   32
#define Hd   512
#define Tt   1000
#define G4   2048
#define NBLK 128
#define JPB  4          // hidden units per block (16 gate rows)
#define NTHR 256
#define PS   40         // part row stride (floats): bank = (8*jj + b) % 32 -> conflict-free

// h broadcast buffer, transposed [k][b], double buffered by step parity.
__device__ float g_hbuf[2][Hd][Bz];
// packed barrier: low 32 = arrive count, high 32 = generation. Replay-safe
// (count always returns to 0, gen compared relatively).
__device__ unsigned long long g_bar = 0ull;

__device__ __forceinline__ unsigned bar_gen_acquire() {
    unsigned long long v;
    asm volatile("ld.acquire.gpu.u64 %0, [%1];" : "=l"(v) : "l"(&g_bar) : "memory");
    return (unsigned)(v >> 32);
}

__device__ __forceinline__ void bar_arrive() {
    unsigned long long old;
    asm volatile("atom.add.release.gpu.u64 %0, [%1], %2;"
                 : "=l"(old) : "l"(&g_bar), "l"(1ull) : "memory");
    if ((unsigned)old == NBLK - 1u) {
        // reset count and bump gen in ONE atomic: +(2^32 - NBLK)
        unsigned long long bump = (1ull << 32) - (unsigned long long)NBLK;
        asm volatile("red.add.release.gpu.u64 [%0], %1;"
                     :: "l"(&g_bar), "l"(bump) : "memory");
    }
}

#define FFMA2(d, a, b) asm("fma.rn.f32x2 %0, %1, %2, %0;" : "+l"(d) : "l"(a), "l"(b))

__device__ __forceinline__ float sigf(float x) {
    return __fdividef(1.0f, 1.0f + __expf(-x));
}
__device__ __forceinline__ float tanhf_fast(float x) {
    float e = __expf(2.0f * x);
    return 1.0f - __fdividef(2.0f, e + 1.0f);
}

__global__ void __launch_bounds__(NTHR, 1)
lstm_persistent(const float* __restrict__ wx, const float* __restrict__ u,
                const float* __restrict__ ub, const float* __restrict__ h0,
                const float* __restrict__ c0, float* __restrict__ out)
{
    extern __shared__ float sm[];
    float* u_dup = sm;                     // [512][32]: row r duplicated at 2r,2r+1 (64KB)
    float* h_shT = u_dup + Hd * 32;        // [512][32]: current h transposed      (64KB)
    float* part  = h_shT + Hd * Bz;        // [8][16*PS]: k-slice partials          (20KB)

    const int tid = threadIdx.x;
    const int blk = blockIdx.x;
    const int j0  = blk * JPB;

    // generation base (must be read before this block's first arrival)
    const unsigned g0 = bar_gen_acquire();

    // ---------------- prologue -------------------------------------------------
    // persistent weights, duplicated along r for free FFMA2 broadcast pairs
    for (int idx = tid; idx < 16 * Hd; idx += NTHR) {
        int r = idx >> 9;                  // local row 0..15
        int k = idx & (Hd - 1);
        int R = ((r >> 2) << 9) + j0 + (r & 3);
        float v = u[(size_t)R * Hd + k];
        u_dup[k * 32 + 2 * r]     = v;
        u_dup[k * 32 + 2 * r + 1] = v;
    }

    const int jj = tid & 3;                // elementwise thread coords (tid < 128)
    const int bb = tid >> 2;
    float c_reg = 0.0f, br0 = 0, br1 = 0, br2 = 0, br3 = 0;
    if (tid < 128) {
        c_reg = c0[(size_t)bb * Hd + j0 + jj];
        br0 = __ldg(&ub[0 * Hd + j0 + jj]);
        br1 = __ldg(&ub[1 * Hd + j0 + jj]);
        br2 = __ldg(&ub[2 * Hd + j0 + jj]);
        br3 = __ldg(&ub[3 * Hd + j0 + jj]);
        g_hbuf[0][j0 + jj][bb] = h0[(size_t)bb * Hd + j0 + jj];
        __threadfence();
    }
    __syncthreads();
    if (tid == 0) bar_arrive();

    // GEMM tiling: 8 warps = 8 k-slices of 64; within warp 32 tiles of 4b x 4r
    const int lane = tid & 31;
    const int ks   = tid >> 5;
    const int bt   = lane & 7;             // batches 4*bt..4*bt+3
    const int rt   = lane >> 3;            // rows    4*rt..4*rt+3
    const int k0   = ks * 64;

    const size_t S = (size_t)Bz * Tt * Hd;

    for (int t = 0; t < Tt; t++) {
        const int p = t & 1;

        // ---- wait for h(t) to be published ----
        {
            const unsigned target = g0 + 1u + (unsigned)t;
            while ((int)(bar_gen_acquire() - target) < 0) { }
        }
        __syncwarp();

        // ---- wx for this step straight to registers (hidden under GEMM) ----
        float wr0 = 0, wr1 = 0, wr2 = 0, wr3 = 0;
        if (tid < 128) {
            const float* wp = wx + ((size_t)bb * Tt + t) * G4 + j0 + jj;
            wr0 = __ldg(wp + 0 * Hd);
            wr1 = __ldg(wp + 1 * Hd);
            wr2 = __ldg(wp + 2 * Hd);
            wr3 = __ldg(wp + 3 * Hd);
        }

        // ---- per-warp h chunk copy: warp ks owns k in [k0, k0+64) only ----
        {
            const float4* src = reinterpret_cast<const float4*>(&g_hbuf[p][k0][0]);
            float4*       dst = reinterpret_cast<float4*>(h_shT + k0 * Bz);
            #pragma unroll
            for (int i = 0; i < 16; i++)
                dst[lane + 32 * i] = __ldcg(src + lane + 32 * i);
        }
        __syncwarp();

        // ---- GEMM (FFMA2): acc[bp][j] lanes = batch pair, broadcast = u row ----
        unsigned long long a00 = 0, a01 = 0, a02 = 0, a03 = 0;
        unsigned long long a10 = 0, a11 = 0, a12 = 0, a13 = 0;
        {
            const float* hP = h_shT + (size_t)k0 * 32 + bt * 4;
            const float* uP = u_dup + (size_t)k0 * 32 + rt * 8;
            #pragma unroll 8
            for (int k = 0; k < 64; k++) {
                ulonglong2 hp = *reinterpret_cast<const ulonglong2*>(hP + k * 32);
                ulonglong2 ua = *reinterpret_cast<const ulonglong2*>(uP + k * 32);
                ulonglong2 ub2 = *reinterpret_cast<const ulonglong2*>(uP + k * 32 + 4);
                FFMA2(a00, hp.x, ua.x);  FFMA2(a10, hp.y, ua.x);
                FFMA2(a01, hp.x, ua.y);  FFMA2(a11, hp.y, ua.y);
                FFMA2(a02, hp.x, ub2.x); FFMA2(a12, hp.y, ub2.x);
                FFMA2(a03, hp.x, ub2.y); FFMA2(a13, hp.y, ub2.y);
            }
        }
        // partial store: u64 -> 2 consecutive batches, stride PS rows
        {
            unsigned long long* pp = reinterpret_cast<unsigned long long*>(
                part + ks * (16 * PS) + (rt * 4) * PS + bt * 4);
            pp[0]            = a00;  pp[1]            = a10;
            pp[PS / 2]       = a01;  pp[PS / 2 + 1]   = a11;
            pp[PS]           = a02;  pp[PS + 1]       = a12;
            pp[3 * PS / 2]   = a03;  pp[3 * PS / 2+1] = a13;
        }
        __syncthreads();

        // ---- fused reduce + LSTM cell (threads 0..127) ----
        if (tid < 128) {
            float s0, s1, s2, s3;
            {
                const float* pp = part + jj * PS + bb;
                #define RED(g, bias, wxr, dst)                                  \
                {   const float* q = pp + (g) * 4 * PS;                          \
                    float t0 = q[0 * 16 * PS] + q[1 * 16 * PS];                  \
                    float t1 = q[2 * 16 * PS] + q[3 * 16 * PS];                  \
                    float t2 = q[4 * 16 * PS] + q[5 * 16 * PS];                  \
                    float t3 = q[6 * 16 * PS] + q[7 * 16 * PS];                  \
                    dst = (wxr + bias) + ((t0 + t1) + (t2 + t3)); }
                RED(0, br0, wr0, s0)
                RED(1, br1, wr1, s1)
                RED(2, br2, wr2, s2)
                RED(3, br3, wr3, s3)
                #undef RED
            }
            float it = sigf(s0);
            float ft = sigf(s1);
            float gt = tanhf_fast(s2);
            float ot = sigf(s3);
            float c  = ft * c_reg + it * gt;
            float h  = ot * tanhf_fast(c);
            c_reg = c;

            // publish h first — only this gates the barrier
            g_hbuf[p ^ 1][j0 + jj][bb] = h;
            __threadfence();

            __syncthreads();
            if (tid == 0) bar_arrive();

            // outputs AFTER arrival: off the inter-block critical path
            size_t base = ((size_t)bb * Tt + t) * Hd + j0 + jj;
            out[base]         = h;
            out[S + base]     = c;
            out[2 * S + base] = it;
            out[3 * S + base] = ft;
            out[4 * S + base] = gt;
            out[5 * S + base] = ot;
        } else {
            __syncthreads();
        }
    }
}

extern "C" void kernel_launch(void* const* d_in, const int* in_sizes, int n_in,
                              void* d_out, int out_size) {
    const float* wx = (const float*)d_in[0];
    const float* u  = (const float*)d_in[1];
    const float* ub = (const float*)d_in[2];
    const float* h0 = (const float*)d_in[3];
    const float* c0 = (const float*)d_in[4];
    float* out = (float*)d_out;

    size_t smem = (size_t)(Hd * 32 + Hd * Bz + 8 * 16 * PS) * sizeof(float); // 151552 B
    cudaFuncSetAttribute(lstm_persistent,
                         cudaFuncAttributeMaxDynamicSharedMemorySize, (int)smem);
    lstm_persistent<<<NBLK, NTHR, smem>>>(wx, u, ub, h0, c0, out);
}